// round 1
// baseline (speedup 1.0000x reference)
#include <cuda_runtime.h>
#include <math.h>

#define NC 23
#define NG 20000
#define NN 64
#define NH 64
#define MAXNNZ (NC * NG)

#define SEGS 4
#define BLK 256
#define WARPS (BLK / 32)

// ---- scratch (static device globals; no allocation in kernel_launch) ----
__device__ int   d_count[NC];
__device__ int   d_offset[NC + 1];
__device__ int   d_cursor[NC];
__device__ int   d_gidx[MAXNNZ];
__device__ float d_gval[MAXNNZ];
__device__ float d_outacc[NN * NC * NH];
__device__ float d_sumw[NN * NC];

// ---------------- preprocessing ----------------

__global__ void k_init() {
    int t = blockIdx.x * blockDim.x + threadIdx.x;
    if (t < NN * NC * NH) d_outacc[t] = 0.f;
    if (t < NN * NC) d_sumw[t] = 0.f;
    if (t < NC) d_count[t] = 0;
}

__global__ void k_hist(const float* __restrict__ chrom) {
    int t = blockIdx.x * blockDim.x + threadIdx.x;
    if (t < NC * NG) {
        if (chrom[t] != 0.f) atomicAdd(&d_count[t / NG], 1);
    }
}

__global__ void k_prefix() {
    if (threadIdx.x == 0 && blockIdx.x == 0) {
        int acc = 0;
        for (int i = 0; i < NC; i++) {
            d_offset[i] = acc;
            d_cursor[i] = acc;
            acc += d_count[i];
        }
        d_offset[NC] = acc;
    }
}

__global__ void k_scatter(const float* __restrict__ chrom) {
    int t = blockIdx.x * blockDim.x + threadIdx.x;
    if (t < NC * NG) {
        float v = chrom[t];
        if (v != 0.f) {
            int i = t / NG;
            int g = t - i * NG;
            int pos = atomicAdd(&d_cursor[i], 1);
            d_gidx[pos] = g;
            d_gval[pos] = v;
        }
    }
}

// ---------------- main fused pass ----------------
// grid: (SEGS, NC, NN). Each half-warp streams genes of chromosome ci for
// batch n: load x-row (256B) as 16 x float4, dot with A[ci], weight, accumulate.

__device__ __forceinline__ void process_gene(
    int p, const float* __restrict__ xbase, const float4 a4,
    unsigned hm, int hl, float4& acc, float& sumw)
{
    int g = d_gidx[p];
    float v = d_gval[p];
    const float4 xv =
        *reinterpret_cast<const float4*>(xbase + (long long)g * NH + hl * 4);
    float s = a4.x * xv.x + a4.y * xv.y + a4.z * xv.z + a4.w * xv.w;
    s += __shfl_xor_sync(hm, s, 8);
    s += __shfl_xor_sync(hm, s, 4);
    s += __shfl_xor_sync(hm, s, 2);
    s += __shfl_xor_sync(hm, s, 1);
    float a = s * v;
    float w = 0.f;
    if (a != 0.f) {
        float lr = a > 0.f ? a : 0.2f * a;   // leaky_relu(0.2)
        w = expf(lr);
    }
    acc.x += w * xv.x;
    acc.y += w * xv.y;
    acc.z += w * xv.z;
    acc.w += w * xv.w;
    sumw += w;
}

__global__ __launch_bounds__(BLK)
void k_main(const float* __restrict__ x, const float* __restrict__ attn) {
    const int seg = blockIdx.x;
    const int ci  = blockIdx.y;
    const int n   = blockIdx.z;

    const int bstart = d_offset[ci];
    const int bend   = d_offset[ci + 1];
    const int cnt    = bend - bstart;
    const int s0 = bstart + (int)((long long)cnt * seg / SEGS);
    const int s1 = bstart + (int)((long long)cnt * (seg + 1) / SEGS);

    const int tid  = threadIdx.x;
    const int wid  = tid >> 5;
    const int lane = tid & 31;
    const int hl   = lane & 15;   // lane within half-warp
    const int half = lane >> 4;
    const unsigned hm = half ? 0xffff0000u : 0x0000ffffu;

    // attention row for this chromosome (4 floats per lane, h = 4*hl .. 4*hl+3)
    const float4 a4 =
        *reinterpret_cast<const float4*>(attn + ci * NH + hl * 4);

    const float* xbase = x + (long long)n * NG * NH;

    float4 acc = make_float4(0.f, 0.f, 0.f, 0.f);
    float sumw = 0.f;

    const int stream = wid * 2 + half;   // 16 half-warp streams per block
    const int step   = 2 * WARPS;        // 16

    // 2-way unrolled independent gene streams for ILP on the shfl/exp chain
    int p = s0 + stream;
    for (; p + step < s1; p += 2 * step) {
        process_gene(p,        xbase, a4, hm, hl, acc, sumw);
        process_gene(p + step, xbase, a4, hm, hl, acc, sumw);
    }
    if (p < s1) process_gene(p, xbase, a4, hm, hl, acc, sumw);

    // combine halves: lanes 0..15 pick up lanes 16..31
    acc.x += __shfl_down_sync(0xffffffffu, acc.x, 16);
    acc.y += __shfl_down_sync(0xffffffffu, acc.y, 16);
    acc.z += __shfl_down_sync(0xffffffffu, acc.z, 16);
    acc.w += __shfl_down_sync(0xffffffffu, acc.w, 16);
    sumw  += __shfl_down_sync(0xffffffffu, sumw, 16);

    // block-level reduction in smem
    __shared__ float s_acc[NH];
    __shared__ float s_sum;
    if (tid < NH) s_acc[tid] = 0.f;
    if (tid == 0) s_sum = 0.f;
    __syncthreads();

    if (lane < 16) {
        atomicAdd(&s_acc[hl * 4 + 0], acc.x);
        atomicAdd(&s_acc[hl * 4 + 1], acc.y);
        atomicAdd(&s_acc[hl * 4 + 2], acc.z);
        atomicAdd(&s_acc[hl * 4 + 3], acc.w);
    }
    if (lane == 0) atomicAdd(&s_sum, sumw);
    __syncthreads();

    float* oacc = d_outacc + ((long long)n * NC + ci) * NH;
    if (tid < NH) atomicAdd(&oacc[tid], s_acc[tid]);
    if (tid == 0) atomicAdd(&d_sumw[n * NC + ci], s_sum);
}

// ---------------- epilogue ----------------

__global__ void k_final(float* __restrict__ out) {
    int t = blockIdx.x * blockDim.x + threadIdx.x;
    if (t < NN * NC * NH) {
        int ni = t / NH;
        float s = d_sumw[ni];
        out[t] = d_outacc[t] / fmaxf(s, 1e-10f);
    }
}

// ---------------- launcher ----------------

extern "C" void kernel_launch(void* const* d_in, const int* in_sizes, int n_in,
                              void* d_out, int out_size) {
    const float* x     = (const float*)d_in[0];   // (N, G, H)
    const float* chrom = (const float*)d_in[1];   // (C, G)
    const float* attn  = (const float*)d_in[2];   // (C, H)
    float* out = (float*)d_out;                   // (N, C, H)

    (void)in_sizes; (void)n_in; (void)out_size;

    // zero accumulators + counts
    k_init<<<(NN * NC * NH + BLK - 1) / BLK, BLK>>>();

    // bucket genes by chromosome (counting sort over nonzeros of chrom_mat)
    int nb = (NC * NG + BLK - 1) / BLK;
    k_hist<<<nb, BLK>>>(chrom);
    k_prefix<<<1, 32>>>();
    k_scatter<<<nb, BLK>>>(chrom);

    // fused attention + weighted accumulation (single pass over x)
    dim3 grid(SEGS, NC, NN);
    k_main<<<grid, BLK>>>(x, attn);

    // normalize
    k_final<<<(NN * NC * NH + BLK - 1) / BLK, BLK>>>(out);
}

// round 2
// speedup vs baseline: 1.2095x; 1.2095x over previous
#include <cuda_runtime.h>
#include <math.h>

#define NC 23
#define NG 20000
#define NN 64
#define NH 64

#define BLKA 256
#define NBLKA ((NG + BLKA - 1) / BLKA)   // 79

#define SEGS 4
#define BLK 256
#define WARPS (BLK / 32)

// ---- scratch (static device globals; no allocation in kernel_launch) ----
__device__ int   d_offset[NC + 1];
__device__ int   d_cursor[NC];
__device__ int   d_blockhist[NBLKA * NC];
__device__ int   d_assign[NG];
__device__ float d_val[NG];
__device__ int2  d_pack[NG];             // (gene idx, gval bits) bucketed
__device__ float d_outacc[NN * NC * NH];
__device__ float d_sumw[NN * NC];

// ---------------- P1: per-gene assignment + per-block hist + zeroing -------

__global__ __launch_bounds__(BLKA)
void k_assign(const float* __restrict__ chrom) {
    __shared__ int s_hist[NC];
    const int tid = threadIdx.x;
    const int g = blockIdx.x * BLKA + tid;

    if (tid < NC) s_hist[tid] = 0;
    __syncthreads();

    int ci = 0;
    if (g < NG) {
        float val = 0.f;
        #pragma unroll
        for (int c = 0; c < NC; c++) {
            float v = chrom[c * NG + g];       // coalesced across g
            if (v != 0.f) { ci = c; val = v; }
        }
        d_assign[g] = ci;
        d_val[g] = val;
        atomicAdd(&s_hist[ci], 1);             // smem only
    }

    // fold accumulator zeroing in (grid-stride over 94208 + 1472 floats)
    const int nt = NBLKA * BLKA;
    for (int i = blockIdx.x * BLKA + tid; i < NN * NC * NH; i += nt)
        d_outacc[i] = 0.f;
    if (blockIdx.x * BLKA + tid < NN * NC)
        d_sumw[blockIdx.x * BLKA + tid] = 0.f;

    __syncthreads();
    if (tid < NC) d_blockhist[blockIdx.x * NC + tid] = s_hist[tid];
}

// ---------------- P2: chromosome totals + exclusive scan (1 warp) ----------

__global__ void k_prefix() {
    const int lane = threadIdx.x;
    int cnt = 0;
    if (lane < NC) {
        #pragma unroll 4
        for (int b = 0; b < NBLKA; b++) cnt += d_blockhist[b * NC + lane];
    }
    int acc = cnt;  // inclusive scan over 32 lanes (lanes >= NC hold 0)
    #pragma unroll
    for (int d = 1; d < 32; d <<= 1) {
        int v = __shfl_up_sync(0xffffffffu, acc, d);
        if (lane >= d) acc += v;
    }
    if (lane < NC) {
        d_offset[lane] = acc - cnt;
        d_cursor[lane] = acc - cnt;
        if (lane == NC - 1) d_offset[NC] = acc;
    }
}

// ---------------- P3: scatter with block-level range reservation -----------

__global__ __launch_bounds__(BLKA)
void k_scatter() {
    __shared__ int s_hist[NC];
    __shared__ int s_base[NC];
    const int tid = threadIdx.x;
    const int g = blockIdx.x * BLKA + tid;

    if (tid < NC) s_hist[tid] = 0;
    __syncthreads();

    int ci = -1;
    if (g < NG) {
        ci = d_assign[g];
        atomicAdd(&s_hist[ci], 1);
    }
    __syncthreads();

    if (tid < NC) {
        int c = s_hist[tid];
        s_base[tid] = (c > 0) ? atomicAdd(&d_cursor[tid], c) : 0;  // 23/block
    }
    __syncthreads();

    if (g < NG) {
        int pos = atomicAdd(&s_base[ci], 1);   // smem cursor
        d_pack[pos] = make_int2(g, __float_as_int(d_val[g]));
    }
}

// ---------------- main fused pass -------------------------------------------
// grid: (SEGS, NC, NN). Each half-warp streams genes of chromosome ci for
// batch n: load x-row (256B) as 16 x float4, dot with A[ci], weight, accumulate.

__device__ __forceinline__ void process_gene(
    int p, const float* __restrict__ xbase, const float4 a4,
    unsigned hm, int hl, float4& acc, float& sumw)
{
    const int2 pk = d_pack[p];
    const int g = pk.x;
    const float v = __int_as_float(pk.y);
    const float4 xv =
        *reinterpret_cast<const float4*>(xbase + (long long)g * NH + hl * 4);
    float s = a4.x * xv.x + a4.y * xv.y + a4.z * xv.z + a4.w * xv.w;
    s += __shfl_xor_sync(hm, s, 8);
    s += __shfl_xor_sync(hm, s, 4);
    s += __shfl_xor_sync(hm, s, 2);
    s += __shfl_xor_sync(hm, s, 1);
    float a = s * v;
    float w = 0.f;
    if (a != 0.f) {
        float lr = a > 0.f ? a : 0.2f * a;   // leaky_relu(0.2)
        w = __expf(lr);
    }
    acc.x += w * xv.x;
    acc.y += w * xv.y;
    acc.z += w * xv.z;
    acc.w += w * xv.w;
    sumw += w;
}

__global__ __launch_bounds__(BLK)
void k_main(const float* __restrict__ x, const float* __restrict__ attn) {
    const int seg = blockIdx.x;
    const int ci  = blockIdx.y;
    const int n   = blockIdx.z;

    const int bstart = d_offset[ci];
    const int bend   = d_offset[ci + 1];
    const int cnt    = bend - bstart;
    const int s0 = bstart + (int)((long long)cnt * seg / SEGS);
    const int s1 = bstart + (int)((long long)cnt * (seg + 1) / SEGS);

    const int tid  = threadIdx.x;
    const int wid  = tid >> 5;
    const int lane = tid & 31;
    const int hl   = lane & 15;   // lane within half-warp
    const int half = lane >> 4;
    const unsigned hm = half ? 0xffff0000u : 0x0000ffffu;

    // attention row for this chromosome (4 floats per lane)
    const float4 a4 =
        *reinterpret_cast<const float4*>(attn + ci * NH + hl * 4);

    const float* xbase = x + (long long)n * NG * NH;

    float4 acc = make_float4(0.f, 0.f, 0.f, 0.f);
    float sumw = 0.f;

    const int stream = wid * 2 + half;   // 16 half-warp streams per block
    const int step   = 2 * WARPS;        // 16

    // 2-way unrolled independent gene iterations for ILP on the shfl/exp chain
    int p = s0 + stream;
    for (; p + step < s1; p += 2 * step) {
        process_gene(p,        xbase, a4, hm, hl, acc, sumw);
        process_gene(p + step, xbase, a4, hm, hl, acc, sumw);
    }
    if (p < s1) process_gene(p, xbase, a4, hm, hl, acc, sumw);

    // combine halves: lanes 0..15 pick up lanes 16..31
    acc.x += __shfl_down_sync(0xffffffffu, acc.x, 16);
    acc.y += __shfl_down_sync(0xffffffffu, acc.y, 16);
    acc.z += __shfl_down_sync(0xffffffffu, acc.z, 16);
    acc.w += __shfl_down_sync(0xffffffffu, acc.w, 16);
    sumw  += __shfl_down_sync(0xffffffffu, sumw, 16);

    // block-level reduction in smem
    __shared__ float s_acc[NH];
    __shared__ float s_sum;
    if (tid < NH) s_acc[tid] = 0.f;
    if (tid == 0) s_sum = 0.f;
    __syncthreads();

    if (lane < 16) {
        atomicAdd(&s_acc[hl * 4 + 0], acc.x);
        atomicAdd(&s_acc[hl * 4 + 1], acc.y);
        atomicAdd(&s_acc[hl * 4 + 2], acc.z);
        atomicAdd(&s_acc[hl * 4 + 3], acc.w);
    }
    if (lane == 0) atomicAdd(&s_sum, sumw);
    __syncthreads();

    float* oacc = d_outacc + ((long long)n * NC + ci) * NH;
    if (tid < NH) atomicAdd(&oacc[tid], s_acc[tid]);
    if (tid == 0) atomicAdd(&d_sumw[n * NC + ci], s_sum);
}

// ---------------- epilogue --------------------------------------------------

__global__ void k_final(float* __restrict__ out) {
    int t = blockIdx.x * blockDim.x + threadIdx.x;
    if (t < NN * NC * NH) {
        int ni = t / NH;
        float s = d_sumw[ni];
        out[t] = d_outacc[t] / fmaxf(s, 1e-10f);
    }
}

// ---------------- launcher --------------------------------------------------

extern "C" void kernel_launch(void* const* d_in, const int* in_sizes, int n_in,
                              void* d_out, int out_size) {
    const float* x     = (const float*)d_in[0];   // (N, G, H)
    const float* chrom = (const float*)d_in[1];   // (C, G)
    const float* attn  = (const float*)d_in[2];   // (C, H)
    float* out = (float*)d_out;                   // (N, C, H)

    (void)in_sizes; (void)n_in; (void)out_size;

    // bucket genes by chromosome (contention-free counting sort) + zero accum
    k_assign<<<NBLKA, BLKA>>>(chrom);
    k_prefix<<<1, 32>>>();
    k_scatter<<<NBLKA, BLKA>>>();

    // fused attention + weighted accumulation (single pass over x)
    dim3 grid(SEGS, NC, NN);
    k_main<<<grid, BLK>>>(x, attn);

    // normalize
    k_final<<<(NN * NC * NH + BLK - 1) / BLK, BLK>>>(out);
}

// round 3
// speedup vs baseline: 1.3566x; 1.1216x over previous
#include <cuda_runtime.h>
#include <math.h>

#define NC 23
#define NG 20000
#define NN 64
#define NH 64

#define BLKA 256
#define NBLKA ((NG + BLKA - 1) / BLKA)   // 79

#define SEGS 4
#define BLK 256
#define WARPS (BLK / 32)
#define STREAMS (WARPS * 2)              // 16 half-warp streams per block

// ---- scratch (static device globals; no allocation in kernel_launch) ----
__device__ int   d_offset[NC + 1];
__device__ int   d_blockhist[NBLKA * NC];
__device__ int   d_assign[NG];
__device__ float d_val[NG];
__device__ int2  d_pack[NG];             // (gene idx, gval bits) bucketed
__device__ float d_outacc[NN * NC * NH];
__device__ float d_sumw[NN * NC];

// ---------------- P1: per-gene assignment + per-block hist + zeroing -------

__global__ __launch_bounds__(BLKA)
void k_assign(const float* __restrict__ chrom) {
    __shared__ int s_hist[NC];
    const int tid = threadIdx.x;
    const int g = blockIdx.x * BLKA + tid;

    if (tid < NC) s_hist[tid] = 0;
    __syncthreads();

    if (g < NG) {
        int ci = 0;
        float val = 0.f;
        #pragma unroll
        for (int c = 0; c < NC; c++) {
            float v = chrom[c * NG + g];       // coalesced across g
            if (v != 0.f) { ci = c; val = v; }
        }
        d_assign[g] = ci;
        d_val[g] = val;
        atomicAdd(&s_hist[ci], 1);             // smem only
    }

    // fold accumulator zeroing in
    const int nt = NBLKA * BLKA;
    for (int i = blockIdx.x * BLKA + tid; i < NN * NC * NH; i += nt)
        d_outacc[i] = 0.f;
    if (blockIdx.x * BLKA + tid < NN * NC)
        d_sumw[blockIdx.x * BLKA + tid] = 0.f;

    __syncthreads();
    if (tid < NC) d_blockhist[blockIdx.x * NC + tid] = s_hist[tid];
}

// ---------------- P2: scatter; each block derives offsets locally ----------

__global__ __launch_bounds__(BLKA)
void k_scatter() {
    __shared__ int s_off[NC];    // exclusive global offset per chromosome
    __shared__ int s_base[NC];   // this block's running cursor per chromosome
    const int tid = threadIdx.x;
    const int bid = blockIdx.x;
    const int g = bid * BLKA + tid;

    // column totals + prefix of earlier blocks (23 threads, 79 ints each; L2 hot)
    int tot = 0, pre = 0;
    if (tid < NC) {
        #pragma unroll 4
        for (int b = 0; b < NBLKA; b++) {
            int h = d_blockhist[b * NC + tid];
            tot += h;
            if (b < bid) pre += h;
        }
    }
    // exclusive scan of tot over 23 lanes (warp 0)
    if (tid < 32) {
        int v = (tid < NC) ? tot : 0;
        int acc = v;
        #pragma unroll
        for (int d = 1; d < 32; d <<= 1) {
            int u = __shfl_up_sync(0xffffffffu, acc, d);
            if (tid >= d) acc += u;
        }
        if (tid < NC) {
            s_off[tid] = acc - v;
            if (bid == 0) {
                d_offset[tid] = acc - v;
                if (tid == NC - 1) d_offset[NC] = acc;
            }
        }
    }
    __syncthreads();
    if (tid < NC) s_base[tid] = s_off[tid] + pre;
    __syncthreads();

    if (g < NG) {
        int ci = d_assign[g];
        int pos = atomicAdd(&s_base[ci], 1);   // smem-only cursor
        d_pack[pos] = make_int2(g, __float_as_int(d_val[g]));
    }
}

// ---------------- main fused pass -------------------------------------------
// grid: (SEGS, NC, NN). Each half-warp streams genes of chromosome ci for
// batch n. 4-way software pipeline: batch 4 pack loads, then 4 row loads,
// then 4 interleaved shfl/exp chains.

__device__ __forceinline__ void compute_gene(
    const float4 xv, const float v, const float4 a4,
    unsigned hm, float4& acc, float& sumw)
{
    float s = a4.x * xv.x + a4.y * xv.y + a4.z * xv.z + a4.w * xv.w;
    s += __shfl_xor_sync(hm, s, 8);
    s += __shfl_xor_sync(hm, s, 4);
    s += __shfl_xor_sync(hm, s, 2);
    s += __shfl_xor_sync(hm, s, 1);
    float a = s * v;
    float w = 0.f;
    if (a != 0.f) {
        float lr = a > 0.f ? a : 0.2f * a;   // leaky_relu(0.2)
        w = __expf(lr);
    }
    acc.x += w * xv.x;
    acc.y += w * xv.y;
    acc.z += w * xv.z;
    acc.w += w * xv.w;
    sumw += w;
}

__global__ __launch_bounds__(BLK)
void k_main(const float* __restrict__ x, const float* __restrict__ attn) {
    const int seg = blockIdx.x;
    const int ci  = blockIdx.y;
    const int n   = blockIdx.z;

    const int bstart = d_offset[ci];
    const int bend   = d_offset[ci + 1];
    const int cnt    = bend - bstart;
    const int s0 = bstart + (int)((long long)cnt * seg / SEGS);
    const int s1 = bstart + (int)((long long)cnt * (seg + 1) / SEGS);

    const int tid  = threadIdx.x;
    const int wid  = tid >> 5;
    const int lane = tid & 31;
    const int hl   = lane & 15;   // lane within half-warp
    const int half = lane >> 4;
    const unsigned hm = half ? 0xffff0000u : 0x0000ffffu;

    const float4 a4 =
        *reinterpret_cast<const float4*>(attn + ci * NH + hl * 4);

    const float* xbase = x + (long long)n * NG * NH;

    float4 acc = make_float4(0.f, 0.f, 0.f, 0.f);
    float sumw = 0.f;

    const int stream = wid * 2 + half;
    const int step   = STREAMS;          // 16

    int p = s0 + stream;

    // 4-way pipelined main loop: front-load all 8 loads, then compute
    for (; p + 3 * step < s1; p += 4 * step) {
        const int2 pk0 = d_pack[p];
        const int2 pk1 = d_pack[p + step];
        const int2 pk2 = d_pack[p + 2 * step];
        const int2 pk3 = d_pack[p + 3 * step];
        const float4 x0 = *reinterpret_cast<const float4*>(
            xbase + (long long)pk0.x * NH + hl * 4);
        const float4 x1 = *reinterpret_cast<const float4*>(
            xbase + (long long)pk1.x * NH + hl * 4);
        const float4 x2 = *reinterpret_cast<const float4*>(
            xbase + (long long)pk2.x * NH + hl * 4);
        const float4 x3 = *reinterpret_cast<const float4*>(
            xbase + (long long)pk3.x * NH + hl * 4);
        compute_gene(x0, __int_as_float(pk0.y), a4, hm, acc, sumw);
        compute_gene(x1, __int_as_float(pk1.y), a4, hm, acc, sumw);
        compute_gene(x2, __int_as_float(pk2.y), a4, hm, acc, sumw);
        compute_gene(x3, __int_as_float(pk3.y), a4, hm, acc, sumw);
    }
    for (; p < s1; p += step) {
        const int2 pk = d_pack[p];
        const float4 xv = *reinterpret_cast<const float4*>(
            xbase + (long long)pk.x * NH + hl * 4);
        compute_gene(xv, __int_as_float(pk.y), a4, hm, acc, sumw);
    }

    // combine halves: lanes 0..15 pick up lanes 16..31
    acc.x += __shfl_down_sync(0xffffffffu, acc.x, 16);
    acc.y += __shfl_down_sync(0xffffffffu, acc.y, 16);
    acc.z += __shfl_down_sync(0xffffffffu, acc.z, 16);
    acc.w += __shfl_down_sync(0xffffffffu, acc.w, 16);
    sumw  += __shfl_down_sync(0xffffffffu, sumw, 16);

    // block-level reduction in smem
    __shared__ float s_acc[NH];
    __shared__ float s_sum;
    if (tid < NH) s_acc[tid] = 0.f;
    if (tid == 0) s_sum = 0.f;
    __syncthreads();

    if (lane < 16) {
        atomicAdd(&s_acc[hl * 4 + 0], acc.x);
        atomicAdd(&s_acc[hl * 4 + 1], acc.y);
        atomicAdd(&s_acc[hl * 4 + 2], acc.z);
        atomicAdd(&s_acc[hl * 4 + 3], acc.w);
    }
    if (lane == 0) atomicAdd(&s_sum, sumw);
    __syncthreads();

    float* oacc = d_outacc + ((long long)n * NC + ci) * NH;
    if (tid < NH) atomicAdd(&oacc[tid], s_acc[tid]);
    if (tid == 0) atomicAdd(&d_sumw[n * NC + ci], s_sum);
}

// ---------------- epilogue --------------------------------------------------

__global__ void k_final(float* __restrict__ out) {
    int t = blockIdx.x * blockDim.x + threadIdx.x;
    if (t < NN * NC * NH) {
        int ni = t / NH;
        float s = d_sumw[ni];
        out[t] = d_outacc[t] / fmaxf(s, 1e-10f);
    }
}

// ---------------- launcher --------------------------------------------------

extern "C" void kernel_launch(void* const* d_in, const int* in_sizes, int n_in,
                              void* d_out, int out_size) {
    const float* x     = (const float*)d_in[0];   // (N, G, H)
    const float* chrom = (const float*)d_in[1];   // (C, G)
    const float* attn  = (const float*)d_in[2];   // (C, H)
    float* out = (float*)d_out;                   // (N, C, H)

    (void)in_sizes; (void)n_in; (void)out_size;

    // bucket genes by chromosome (contention-free counting sort) + zero accum
    k_assign<<<NBLKA, BLKA>>>(chrom);
    k_scatter<<<NBLKA, BLKA>>>();

    // fused attention + weighted accumulation (single pass over x)
    dim3 grid(SEGS, NC, NN);
    k_main<<<grid, BLK>>>(x, attn);

    // normalize
    k_final<<<(NN * NC * NH + BLK - 1) / BLK, BLK>>>(out);
}